// round 14
// baseline (speedup 1.0000x reference)
#include <cstdint>
#include <cuda_runtime.h>
#include <cuda_bf16.h>
#include <math.h>

#define NB 4096
#define NHIST 50
#define ALLD 192
#define TRI 18528
#define OUTD 18592
#define TOP1N 1024
#define TOP2N 512
#define NPAIR (OUTD / 2)
#define NCH 581            // 18592 / 32 exactly

__device__ float g_h [NB * 256];
__device__ float g_z [NB * 64];
__device__ float g_mu[64];
__device__ float g_rs[64];
__device__ float g_bh[NB * 512];
__device__ float g_c [NB * ALLD];
__device__ float g_t1[NB * TOP1N];
__device__ float g_t2[NB * TOP2N];
__device__ unsigned short g_lut[OUTD];
__device__ unsigned g_plut[NPAIR];
// interaction matrix, bf16x2, block layout [mblk=32][ch=581][m=128][k2=16]
__device__ unsigned g_at[(size_t)32 * NCH * 2048];
// tw1 bf16x2, block layout [nblk=4][ch=581][k2=16][n=256]
__device__ unsigned g_btb[(size_t)4 * NCH * 4096];

// ---------------- helpers ----------------
__device__ __forceinline__ unsigned f2tf32(float x) {
    unsigned r; asm("cvt.rna.tf32.f32 %0, %1;" : "=r"(r) : "f"(x)); return r;
}
__device__ __forceinline__ unsigned pk(float lo, float hi) {
    unsigned r; asm("cvt.rn.bf16x2.f32 %0, %1, %2;" : "=r"(r) : "f"(hi), "f"(lo)); return r;
}
__device__ __forceinline__ void mma_tf32(float* d, const unsigned* a, unsigned b0, unsigned b1) {
    asm volatile("mma.sync.aligned.m16n8k8.row.col.f32.tf32.tf32.f32 "
        "{%0,%1,%2,%3}, {%4,%5,%6,%7}, {%8,%9}, {%0,%1,%2,%3};\n"
        : "+f"(d[0]), "+f"(d[1]), "+f"(d[2]), "+f"(d[3])
        : "r"(a[0]), "r"(a[1]), "r"(a[2]), "r"(a[3]), "r"(b0), "r"(b1));
}
__device__ __forceinline__ void mma_bf16(float* d, const unsigned* a, unsigned b0, unsigned b1) {
    asm volatile("mma.sync.aligned.m16n8k16.row.col.f32.bf16.bf16.f32 "
        "{%0,%1,%2,%3}, {%4,%5,%6,%7}, {%8,%9}, {%0,%1,%2,%3};\n"
        : "+f"(d[0]), "+f"(d[1]), "+f"(d[2]), "+f"(d[3])
        : "r"(a[0]), "r"(a[1]), "r"(a[2]), "r"(a[3]), "r"(b0), "r"(b1));
}
__device__ __forceinline__ uint32_t smem_u32(const void* p) {
    uint32_t a;
    asm("{ .reg .u64 t; cvta.to.shared.u64 t, %1; cvt.u32.u64 %0, t; }" : "=r"(a) : "l"(p));
    return a;
}

__global__ void lut_init_kernel() {
    int i = threadIdx.x;
    if (i < 192) {
        int off = i * 192 - (i * (i - 1)) / 2;
        for (int j = i; j < 192; ++j)
            g_lut[off + (j - i)] = (unsigned short)(i | (j << 8));
    }
    if (i < 64) g_lut[TRI + i] = (unsigned short)(i | (192 << 8));
}
__global__ void plut_init_kernel() {
    int p = blockIdx.x * blockDim.x + threadIdx.x;
    if (p < NPAIR)
        g_plut[p] = (unsigned)g_lut[2 * p] | ((unsigned)g_lut[2 * p + 1] << 16);
}

__global__ void embed_kernel(const int* __restrict__ xs, const float* __restrict__ emb,
                             float* __restrict__ c) {
    int t = blockIdx.x * blockDim.x + threadIdx.x;
    int b = t >> 4, v = t & 15;
    if (b >= NB) return;
    const float4* et = (const float4*)emb;
    const int* row = xs + b * NHIST;
    float4 acc = make_float4(0.f, 0.f, 0.f, 0.f);
    for (int h = 0; h < NHIST; ++h) {
        float4 e = et[(size_t)row[h] * 16 + v];
        acc.x += e.x; acc.y += e.y; acc.z += e.z; acc.w += e.w;
    }
    *(float4*)(c + (size_t)b * ALLD + 128 + v * 4) = acc;
}

// ---------------- pipelined small GEMM: tile 64x64x32, tf32, 4-stage cp.async ----------
#define GS_SMEM 71680
template<int ACT, int RNA>
__global__ void __launch_bounds__(256) gemm_s(
    const float* __restrict__ A, const float* __restrict__ Bw,
    const float* __restrict__ bias, float* __restrict__ C,
    int N, int K, int ldc)
{
    extern __shared__ unsigned smU[];
    const int tid = threadIdx.x;
    const int warp = tid >> 5, lane = tid & 31;
    const int g = lane >> 2, tg = lane & 3;
    const int wm = warp & 1, wn = warp >> 1;
    const int m0 = blockIdx.y * 64, n0 = blockIdx.x * 64;
    const uint32_t sbase = smem_u32(smU);
    float acc[2][2][4] = {};

#define LOAD_SM(cc) do { \
        int _s = (cc) & 3; \
        uint32_t _da = sbase + _s * 9216; \
        _Pragma("unroll") \
        for (int _q = 0; _q < 2; ++_q) { \
            int _i = tid + _q * 256, _ar = _i >> 3, _a4 = _i & 7; \
            asm volatile("cp.async.cg.shared.global [%0], [%1], 16;" \
                :: "r"(_da + (_ar * 36 + _a4 * 4) * 4), \
                   "l"(A + (size_t)(m0 + _ar) * K + (cc) * 32 + _a4 * 4) : "memory"); \
        } \
        uint32_t _db = sbase + 36864 + _s * 8704; \
        _Pragma("unroll") \
        for (int _q = 0; _q < 2; ++_q) { \
            int _i = tid + _q * 256, _br = _i >> 4, _b4 = _i & 15; \
            asm volatile("cp.async.cg.shared.global [%0], [%1], 16;" \
                :: "r"(_db + (_br * 68 + _b4 * 4) * 4), \
                   "l"(Bw + (size_t)((cc) * 32 + _br) * N + n0 + _b4 * 4) : "memory"); \
        } \
    } while (0)

    const int nch = K / 32;
    LOAD_SM(0); asm volatile("cp.async.commit_group;" ::: "memory");
    LOAD_SM(1); asm volatile("cp.async.commit_group;" ::: "memory");

    for (int c = 0; c < nch; ++c) {
        if (c + 2 < nch) LOAD_SM(c + 2);
        asm volatile("cp.async.commit_group;" ::: "memory");
        asm volatile("cp.async.wait_group 2;" ::: "memory");
        __syncthreads();
        const unsigned* As = smU + (c & 3) * 2304;
        const unsigned* Bs = smU + 9216 + (c & 3) * 2176;
#pragma unroll
        for (int k8 = 0; k8 < 4; ++k8) {
            const int kk = k8 * 8 + tg;
            unsigned a[2][4];
#pragma unroll
            for (int mt = 0; mt < 2; ++mt) {
                int r = (wm * 32 + mt * 16 + g) * 36;
                a[mt][0] = As[r + kk];
                a[mt][1] = As[r + 288 + kk];
                a[mt][2] = As[r + kk + 4];
                a[mt][3] = As[r + 288 + kk + 4];
                if (RNA) {
#pragma unroll
                    for (int q = 0; q < 4; ++q)
                        a[mt][q] = f2tf32(__uint_as_float(a[mt][q]));
                }
            }
#pragma unroll
            for (int nt = 0; nt < 2; ++nt) {
                int col = wn * 16 + nt * 8 + g;
                unsigned b0 = Bs[kk * 68 + col];
                unsigned b1 = Bs[(kk + 4) * 68 + col];
                if (RNA) {
                    b0 = f2tf32(__uint_as_float(b0));
                    b1 = f2tf32(__uint_as_float(b1));
                }
                mma_tf32(acc[0][nt], a[0], b0, b1);
                mma_tf32(acc[1][nt], a[1], b0, b1);
            }
        }
    }
#pragma unroll
    for (int mt = 0; mt < 2; ++mt) {
        int r0 = m0 + wm * 32 + mt * 16 + g;
#pragma unroll
        for (int nt = 0; nt < 2; ++nt) {
            int col = n0 + wn * 16 + nt * 8 + tg * 2;
            float bi0 = bias[col], bi1 = bias[col + 1];
            float v0 = acc[mt][nt][0] + bi0, v1 = acc[mt][nt][1] + bi1;
            float v2 = acc[mt][nt][2] + bi0, v3 = acc[mt][nt][3] + bi1;
            if (ACT) { v0 = fmaxf(v0, 0.f); v1 = fmaxf(v1, 0.f); v2 = fmaxf(v2, 0.f); v3 = fmaxf(v3, 0.f); }
            *(float2*)(C + (size_t)r0 * ldc + col) = make_float2(v0, v1);
            *(float2*)(C + (size_t)(r0 + 8) * ldc + col) = make_float2(v2, v3);
        }
    }
#undef LOAD_SM
}

// ---------------- small GEMM, tile 32x64x32 (for N=64 layers; doubles grid) ----------
#define GS32_SMEM 53248
template<int ACT, int RNA>
__global__ void __launch_bounds__(256) gemm_s32(
    const float* __restrict__ A, const float* __restrict__ Bw,
    const float* __restrict__ bias, float* __restrict__ C,
    int N, int K, int ldc)
{
    extern __shared__ unsigned smU[];
    const int tid = threadIdx.x;
    const int warp = tid >> 5, lane = tid & 31;
    const int g = lane >> 2, tg = lane & 3;
    const int wm = warp & 1, wn = warp >> 1;
    const int m0 = blockIdx.y * 32, n0 = blockIdx.x * 64;
    const uint32_t sbase = smem_u32(smU);
    float acc[2][4] = {};

#define LOAD_S32(cc) do { \
        int _s = (cc) & 3; \
        uint32_t _da = sbase + _s * 13312; \
        { \
            int _ar = tid >> 3, _a4 = tid & 7; \
            asm volatile("cp.async.cg.shared.global [%0], [%1], 16;" \
                :: "r"(_da + (_ar * 36 + _a4 * 4) * 4), \
                   "l"(A + (size_t)(m0 + _ar) * K + (cc) * 32 + _a4 * 4) : "memory"); \
        } \
        uint32_t _db = _da + 4608; \
        _Pragma("unroll") \
        for (int _q = 0; _q < 2; ++_q) { \
            int _i = tid + _q * 256, _br = _i >> 4, _b4 = _i & 15; \
            asm volatile("cp.async.cg.shared.global [%0], [%1], 16;" \
                :: "r"(_db + (_br * 68 + _b4 * 4) * 4), \
                   "l"(Bw + (size_t)((cc) * 32 + _br) * N + n0 + _b4 * 4) : "memory"); \
        } \
    } while (0)

    const int nch = K / 32;
    LOAD_S32(0); asm volatile("cp.async.commit_group;" ::: "memory");
    LOAD_S32(1); asm volatile("cp.async.commit_group;" ::: "memory");

    for (int c = 0; c < nch; ++c) {
        if (c + 2 < nch) LOAD_S32(c + 2);
        asm volatile("cp.async.commit_group;" ::: "memory");
        asm volatile("cp.async.wait_group 2;" ::: "memory");
        __syncthreads();
        const unsigned* As = smU + (c & 3) * 3328;
        const unsigned* Bs = As + 1152;
#pragma unroll
        for (int k8 = 0; k8 < 4; ++k8) {
            const int kk = k8 * 8 + tg;
            unsigned a[4];
            {
                int r = (wm * 16 + g) * 36;
                a[0] = As[r + kk];
                a[1] = As[r + 288 + kk];
                a[2] = As[r + kk + 4];
                a[3] = As[r + 288 + kk + 4];
                if (RNA) {
#pragma unroll
                    for (int q = 0; q < 4; ++q) a[q] = f2tf32(__uint_as_float(a[q]));
                }
            }
#pragma unroll
            for (int nt = 0; nt < 2; ++nt) {
                int col = wn * 16 + nt * 8 + g;
                unsigned b0 = Bs[kk * 68 + col];
                unsigned b1 = Bs[(kk + 4) * 68 + col];
                if (RNA) {
                    b0 = f2tf32(__uint_as_float(b0));
                    b1 = f2tf32(__uint_as_float(b1));
                }
                mma_tf32(acc[nt], a, b0, b1);
            }
        }
    }
    {
        int r0 = m0 + wm * 16 + g;
#pragma unroll
        for (int nt = 0; nt < 2; ++nt) {
            int col = n0 + wn * 16 + nt * 8 + tg * 2;
            float bi0 = bias[col], bi1 = bias[col + 1];
            float v0 = acc[nt][0] + bi0, v1 = acc[nt][1] + bi1;
            float v2 = acc[nt][2] + bi0, v3 = acc[nt][3] + bi1;
            if (ACT) { v0 = fmaxf(v0, 0.f); v1 = fmaxf(v1, 0.f); v2 = fmaxf(v2, 0.f); v3 = fmaxf(v3, 0.f); }
            *(float2*)(C + (size_t)r0 * ldc + col) = make_float2(v0, v1);
            *(float2*)(C + (size_t)(r0 + 8) * ldc + col) = make_float2(v2, v3);
        }
    }
#undef LOAD_S32
}

__global__ void bn_stats_kernel(const float* __restrict__ z) {
    __shared__ float ssum[256], ssq[256];
    int j = blockIdx.x;
    float s = 0.f, q = 0.f;
    for (int b = threadIdx.x; b < NB; b += 256) {
        float v = z[(size_t)b * 64 + j];
        s += v; q += v * v;
    }
    ssum[threadIdx.x] = s; ssq[threadIdx.x] = q;
    __syncthreads();
    for (int o = 128; o > 0; o >>= 1) {
        if (threadIdx.x < o) {
            ssum[threadIdx.x] += ssum[threadIdx.x + o];
            ssq[threadIdx.x]  += ssq[threadIdx.x + o];
        }
        __syncthreads();
    }
    if (threadIdx.x == 0) {
        float m = ssum[0] * (1.f / NB);
        g_mu[j] = m;
        g_rs[j] = rsqrtf(ssq[0] * (1.f / NB) - m * m + 1e-5f);
    }
}

__global__ void bn_apply_kernel(const float* __restrict__ z,
                                const float* __restrict__ gamma,
                                const float* __restrict__ beta,
                                float* __restrict__ c, float* __restrict__ outx) {
    int idx = blockIdx.x * blockDim.x + threadIdx.x;
    if (idx >= NB * 64) return;
    int b = idx >> 6, j = idx & 63;
    float v = gamma[j] * (z[idx] - g_mu[j]) * g_rs[j] + beta[j];
    c[(size_t)b * ALLD + 64 + j] = v;
    if (outx) outx[idx] = v;
}

// ---------------- materialize interaction matrix, layout [mb][ch][m][k2] ----------------
#define AGEN_SMEM (193 * 129 * 4)
__global__ void __launch_bounds__(256) agen_kernel(const float* __restrict__ cbuf,
                                                   unsigned* __restrict__ At, int mb0) {
    extern __shared__ float ct[];
    const int mb = blockIdx.x + mb0, kg = blockIdx.y;
    const int tid = threadIdx.x;
    for (int idx = tid; idx < 128 * 192; idx += 256) {
        int m = idx / 192, j = idx % 192;
        ct[j * 129 + m] = cbuf[(size_t)((size_t)mb * 128 + m) * ALLD + j];
    }
    for (int m = tid; m < 128; m += 256) ct[192 * 129 + m] = 1.0f;
    __syncthreads();
    const int m = tid & 127, half = tid >> 7;
    int ch0 = kg * 73, ch1 = ch0 + 73; if (ch1 > NCH) ch1 = NCH;
    for (int ch = ch0; ch < ch1; ++ch) {
        uint4* dst4 = (uint4*)(At + (((size_t)mb * NCH + ch) << 11));
        unsigned v[8];
#pragma unroll
        for (int k2l = 0; k2l < 8; ++k2l) {
            unsigned pp = g_plut[ch * 16 + half * 8 + k2l];
            int i0 = pp & 255, j0 = (pp >> 8) & 255;
            int i1 = (pp >> 16) & 255, j1 = pp >> 24;
            v[k2l] = pk(ct[i0 * 129 + m] * ct[j0 * 129 + m],
                        ct[i1 * 129 + m] * ct[j1 * 129 + m]);
        }
        dst4[m * 4 + half * 2 + 0] = make_uint4(v[0], v[1], v[2], v[3]);
        dst4[m * 4 + half * 2 + 1] = make_uint4(v[4], v[5], v[6], v[7]);
    }
}

// ---------------- tw1 -> bf16x2 block layout [nblk][ch][k2][n] ----------------
__global__ void __launch_bounds__(256) bprep_kernel(const float* __restrict__ w,
                                                    unsigned* __restrict__ Bt) {
    const int ch = blockIdx.x, nb = blockIdx.y, n = threadIdx.x;
    unsigned* dst = Bt + (((size_t)nb * NCH + ch) << 12);
    const float* src = w + (size_t)ch * 32 * TOP1N + nb * 256 + n;
#pragma unroll
    for (int k2 = 0; k2 < 16; ++k2) {
        float lo = src[(size_t)(2 * k2) * TOP1N];
        float hi = src[(size_t)(2 * k2 + 1) * TOP1N];
        dst[k2 * 256 + n] = pk(lo, hi);
    }
}

// ---------------- big GEMM: t1 = relu(A @ tw1 + tb1), 128x256 tile, ldmatrix A ----------
#define A_STRU 20                      // uints per m-row (80 B, conflict-free LDSM)
#define A_SLOTU (128 * A_STRU)         // 2560 uints = 10240 B
#define GB_STR 264
#define GB_SLOTU (16 * GB_STR)         // 4224 uints = 16896 B
#define GB_BASEU (4 * A_SLOTU)         // 10240 uints
#define G2_SMEM ((4 * A_SLOTU + 4 * GB_SLOTU) * 4)   // 108544 B

__global__ void __launch_bounds__(256, 1) big_gemm2(
    const unsigned* __restrict__ At, const unsigned* __restrict__ Bt,
    const float* __restrict__ tb1, float* __restrict__ t1, int mb0)
{
    extern __shared__ unsigned sm2[];
    const int tid = threadIdx.x, warp = tid >> 5, lane = tid & 31;
    const int g = lane >> 2, tg = lane & 3;
    const int wm = warp & 1, wn = warp >> 1;
    const int nb = blockIdx.x, mb = blockIdx.y + mb0;
    const uint32_t sbase = smem_u32(sm2);
    const char* Ab = (const char*)(At + (((size_t)mb * NCH) << 11));
    const char* Bb = (const char*)(Bt + (((size_t)nb * NCH) << 12));
    const uint32_t lmoff = ((lane & 15) * A_STRU + (lane >> 4) * 4) * 4;   // bytes

    float acc[4][8][4] = {};

#define LOAD_CHUNK(ch) do { \
        int _slot = (ch) & 3; \
        uint32_t _da = sbase + _slot * (A_SLOTU * 4); \
        const char* _sa = Ab + (size_t)(ch) * 8192; \
        _Pragma("unroll") \
        for (int _q = 0; _q < 2; ++_q) { \
            int _gi = _q * 256 + tid, _m = _gi >> 2, _sg = _gi & 3; \
            asm volatile("cp.async.cg.shared.global [%0], [%1], 16;" \
                :: "r"(_da + _m * 80 + _sg * 16), "l"(_sa + _gi * 16) : "memory"); \
        } \
        uint32_t _db = sbase + GB_BASEU * 4 + _slot * (GB_SLOTU * 4); \
        const char* _sb = Bb + (size_t)(ch) * 16384; \
        _Pragma("unroll") \
        for (int _q = 0; _q < 4; ++_q) { \
            int _gi = _q * 256 + tid, _k2 = _gi >> 6, _i = _gi & 63; \
            asm volatile("cp.async.cg.shared.global [%0], [%1], 16;" \
                :: "r"(_db + _k2 * 1056 + _i * 16), "l"(_sb + _gi * 16) : "memory"); \
        } \
    } while (0)

    LOAD_CHUNK(0); asm volatile("cp.async.commit_group;" ::: "memory");
    LOAD_CHUNK(1); asm volatile("cp.async.commit_group;" ::: "memory");

    for (int ch = 0; ch < NCH; ++ch) {
        if (ch + 2 < NCH) LOAD_CHUNK(ch + 2);
        asm volatile("cp.async.commit_group;" ::: "memory");
        asm volatile("cp.async.wait_group 2;" ::: "memory");
        __syncthreads();
        const uint32_t Ab_s = sbase + (ch & 3) * (A_SLOTU * 4);
        const unsigned* Bs = sm2 + GB_BASEU + (ch & 3) * GB_SLOTU;
#pragma unroll
        for (int ks = 0; ks < 2; ++ks) {
            unsigned af[4][4];
#pragma unroll
            for (int mt = 0; mt < 4; ++mt) {
                uint32_t ad = Ab_s + (wm * 64 + mt * 16) * 80 + ks * 32 + lmoff;
                asm volatile("ldmatrix.sync.aligned.m8n8.x4.shared.b16 {%0,%1,%2,%3}, [%4];"
                    : "=r"(af[mt][0]), "=r"(af[mt][1]), "=r"(af[mt][2]), "=r"(af[mt][3])
                    : "r"(ad));
            }
            const int kb = (ks * 8 + tg) * GB_STR + wn * 64 + g;
#pragma unroll
            for (int nt = 0; nt < 8; ++nt) {
                unsigned b0 = Bs[kb + nt * 8];
                unsigned b1 = Bs[kb + nt * 8 + 4 * GB_STR];
#pragma unroll
                for (int mt = 0; mt < 4; ++mt)
                    mma_bf16(acc[mt][nt], af[mt], b0, b1);
            }
        }
    }

    const int m0 = mb * 128, n0 = nb * 256;
#pragma unroll
    for (int mt = 0; mt < 4; ++mt) {
        int r0 = m0 + wm * 64 + mt * 16 + g;
#pragma unroll
        for (int nt = 0; nt < 8; ++nt) {
            int col = n0 + wn * 64 + nt * 8 + tg * 2;
            float bi0 = tb1[col], bi1 = tb1[col + 1];
            *(float2*)(t1 + (size_t)r0 * TOP1N + col) =
                make_float2(fmaxf(acc[mt][nt][0] + bi0, 0.f), fmaxf(acc[mt][nt][1] + bi1, 0.f));
            *(float2*)(t1 + (size_t)(r0 + 8) * TOP1N + col) =
                make_float2(fmaxf(acc[mt][nt][2] + bi0, 0.f), fmaxf(acc[mt][nt][3] + bi1, 0.f));
        }
    }
#undef LOAD_CHUNK
}

__global__ void top3_kernel(const float* __restrict__ t2, const float* __restrict__ w3,
                            const float* __restrict__ b3, float* __restrict__ out) {
    int gw = (blockIdx.x * blockDim.x + threadIdx.x) >> 5;
    int lane = threadIdx.x & 31;
    if (gw >= NB) return;
    const float* r = t2 + (size_t)gw * TOP2N;
    float s = 0.f;
#pragma unroll
    for (int i = 0; i < TOP2N / 32; ++i)
        s = fmaf(r[lane + 32 * i], w3[lane + 32 * i], s);
#pragma unroll
    for (int o = 16; o > 0; o >>= 1) s += __shfl_xor_sync(0xffffffffu, s, o);
    if (lane == 0) out[gw] = 1.f / (1.f + expf(-(s + b3[0])));
}

extern "C" void kernel_launch(void* const* d_in, const int* in_sizes, int n_in,
                              void* d_out, int out_size) {
    const int*   xs    = (const int*)  d_in[0];
    const float* xd    = (const float*)d_in[1];
    const float* xep   = (const float*)d_in[2];
    const float* emb   = (const float*)d_in[3];
    const float* pw1   = (const float*)d_in[4];
    const float* pb1   = (const float*)d_in[5];
    const float* pw2   = (const float*)d_in[6];
    const float* pb2   = (const float*)d_in[7];
    const float* gamma = (const float*)d_in[8];
    const float* beta  = (const float*)d_in[9];
    const float* bw1   = (const float*)d_in[10];
    const float* bb1   = (const float*)d_in[11];
    const float* bw2   = (const float*)d_in[12];
    const float* bb2   = (const float*)d_in[13];
    const float* tw1   = (const float*)d_in[14];
    const float* tb1   = (const float*)d_in[15];
    const float* tw2   = (const float*)d_in[16];
    const float* tb2   = (const float*)d_in[17];
    const float* tw3   = (const float*)d_in[18];
    const float* tb3   = (const float*)d_in[19];
    float* out = (float*)d_out;

    float *h_p, *z_p, *bh_p, *c_p, *t1_p, *t2_p;
    unsigned *at_p, *btb_p;
    cudaGetSymbolAddress((void**)&h_p,  g_h);
    cudaGetSymbolAddress((void**)&z_p,  g_z);
    cudaGetSymbolAddress((void**)&bh_p, g_bh);
    cudaGetSymbolAddress((void**)&c_p,  g_c);
    cudaGetSymbolAddress((void**)&t1_p, g_t1);
    cudaGetSymbolAddress((void**)&t2_p, g_t2);
    cudaGetSymbolAddress((void**)&at_p, g_at);
    cudaGetSymbolAddress((void**)&btb_p, g_btb);

    float* xemb = (out_size >= NB + NB * 64) ? (out + NB) : nullptr;

    static cudaStream_t s1 = nullptr, s2 = nullptr;
    static cudaEvent_t e0 = nullptr, e1 = nullptr, e2 = nullptr,
                       ea0 = nullptr, ea1 = nullptr, e3 = nullptr, e4 = nullptr;
    if (!s1) {
        cudaStreamCreateWithFlags(&s1, cudaStreamNonBlocking);
        cudaStreamCreateWithFlags(&s2, cudaStreamNonBlocking);
        cudaEventCreateWithFlags(&e0, cudaEventDisableTiming);
        cudaEventCreateWithFlags(&e1, cudaEventDisableTiming);
        cudaEventCreateWithFlags(&e2, cudaEventDisableTiming);
        cudaEventCreateWithFlags(&ea0, cudaEventDisableTiming);
        cudaEventCreateWithFlags(&ea1, cudaEventDisableTiming);
        cudaEventCreateWithFlags(&e3, cudaEventDisableTiming);
        cudaEventCreateWithFlags(&e4, cudaEventDisableTiming);
        cudaFuncSetAttribute(gemm_s<1, 1>, cudaFuncAttributeMaxDynamicSharedMemorySize, GS_SMEM);
        cudaFuncSetAttribute(gemm_s<1, 0>, cudaFuncAttributeMaxDynamicSharedMemorySize, GS_SMEM);
        cudaFuncSetAttribute(gemm_s32<0, 1>, cudaFuncAttributeMaxDynamicSharedMemorySize, GS32_SMEM);
        cudaFuncSetAttribute(gemm_s32<1, 0>, cudaFuncAttributeMaxDynamicSharedMemorySize, GS32_SMEM);
        cudaFuncSetAttribute(agen_kernel, cudaFuncAttributeMaxDynamicSharedMemorySize, AGEN_SMEM);
        cudaFuncSetAttribute(big_gemm2, cudaFuncAttributeMaxDynamicSharedMemorySize, G2_SMEM);
    }

    // fork: proj chain on s1, bottom chain on s2, rest on main
    cudaEventRecord(e0, 0);
    cudaStreamWaitEvent(s1, e0, 0);
    cudaStreamWaitEvent(s2, e0, 0);

    // s1: proj (tf32-rna) -> bn -> x_embed
    gemm_s<1, 1><<<dim3(4, 64), 256, GS_SMEM, s1>>>(xep, pw1, pb1, h_p, 256, 768, 256);
    gemm_s32<0, 1><<<dim3(1, 128), 256, GS32_SMEM, s1>>>(h_p, pw2, pb2, z_p, 64, 256, 64);
    bn_stats_kernel<<<64, 256, 0, s1>>>(z_p);
    bn_apply_kernel<<<(NB * 64) / 256, 256, 0, s1>>>(z_p, gamma, beta, c_p, xemb);

    // s2: bottom (tf32-trunc)
    gemm_s<1, 0><<<dim3(8, 64), 256, GS_SMEM, s2>>>(xd, bw1, bb1, bh_p, 512, 256, 512);
    gemm_s32<1, 0><<<dim3(1, 128), 256, GS32_SMEM, s2>>>(bh_p, bw2, bb2, c_p, 64, 512, ALLD);

    // main: luts, weight prep, embedding
    lut_init_kernel<<<1, 192>>>();
    plut_init_kernel<<<(NPAIR + 255) / 256, 256>>>();
    bprep_kernel<<<dim3(NCH, 4), 256>>>(tw1, btb_p);
    embed_kernel<<<(NB * 16) / 256, 256>>>(xs, emb, c_p);

    // join front
    cudaEventRecord(e1, s1);
    cudaEventRecord(e2, s2);
    cudaStreamWaitEvent(0, e1, 0);
    cudaStreamWaitEvent(0, e2, 0);

    // agen halves on main; big halves overlap on s1/s2
    agen_kernel<<<dim3(16, 8), 256, AGEN_SMEM>>>(c_p, at_p, 0);
    cudaEventRecord(ea0, 0);
    agen_kernel<<<dim3(16, 8), 256, AGEN_SMEM>>>(c_p, at_p, 16);
    cudaEventRecord(ea1, 0);

    cudaStreamWaitEvent(s1, ea0, 0);
    big_gemm2<<<dim3(4, 16), 256, G2_SMEM, s1>>>(at_p, btb_p, tb1, t1_p, 0);
    cudaStreamWaitEvent(s2, ea1, 0);
    big_gemm2<<<dim3(4, 16), 256, G2_SMEM, s2>>>(at_p, btb_p, tb1, t1_p, 16);

    cudaEventRecord(e3, s1);
    cudaEventRecord(e4, s2);
    cudaStreamWaitEvent(0, e3, 0);
    cudaStreamWaitEvent(0, e4, 0);

    // top2 (tf32-trunc) + top3
    gemm_s<1, 0><<<dim3(8, 64), 256, GS_SMEM>>>(t1_p, tw2, tb2, t2_p, 512, 1024, 512);
    top3_kernel<<<(NB * 32) / 256, 256>>>(t2_p, tw3, tb3, out);
}

// round 15
// speedup vs baseline: 1.0600x; 1.0600x over previous
#include <cstdint>
#include <cuda_runtime.h>
#include <cuda_bf16.h>
#include <math.h>

#define NB 4096
#define NHIST 50
#define ALLD 192
#define TRI 18528
#define OUTD 18592
#define TOP1N 1024
#define TOP2N 512
#define NPAIR (OUTD / 2)
#define NCH 581            // 18592 / 32 exactly

__device__ float g_h [NB * 256];
__device__ float g_z [NB * 64];
__device__ float g_mu[64];
__device__ float g_rs[64];
__device__ float g_bh[NB * 512];
__device__ float g_c [NB * ALLD];
__device__ float g_t1[NB * TOP1N];
__device__ float g_t2[NB * TOP2N];
__device__ unsigned short g_lut[OUTD];
__device__ unsigned g_plut[NPAIR];
// interaction matrix, bf16x2, block layout [mblk=32][ch=581][m=128][k2=16]
__device__ unsigned g_at[(size_t)32 * NCH * 2048];
// tw1 bf16x2, block layout [nblk=4][ch=581][k2=16][n=256]
__device__ unsigned g_btb[(size_t)4 * NCH * 4096];

// ---------------- helpers ----------------
__device__ __forceinline__ unsigned f2tf32(float x) {
    unsigned r; asm("cvt.rna.tf32.f32 %0, %1;" : "=r"(r) : "f"(x)); return r;
}
__device__ __forceinline__ unsigned pk(float lo, float hi) {
    unsigned r; asm("cvt.rn.bf16x2.f32 %0, %1, %2;" : "=r"(r) : "f"(hi), "f"(lo)); return r;
}
__device__ __forceinline__ void mma_tf32(float* d, const unsigned* a, unsigned b0, unsigned b1) {
    asm volatile("mma.sync.aligned.m16n8k8.row.col.f32.tf32.tf32.f32 "
        "{%0,%1,%2,%3}, {%4,%5,%6,%7}, {%8,%9}, {%0,%1,%2,%3};\n"
        : "+f"(d[0]), "+f"(d[1]), "+f"(d[2]), "+f"(d[3])
        : "r"(a[0]), "r"(a[1]), "r"(a[2]), "r"(a[3]), "r"(b0), "r"(b1));
}
__device__ __forceinline__ void mma_bf16(float* d, const unsigned* a, unsigned b0, unsigned b1) {
    asm volatile("mma.sync.aligned.m16n8k16.row.col.f32.bf16.bf16.f32 "
        "{%0,%1,%2,%3}, {%4,%5,%6,%7}, {%8,%9}, {%0,%1,%2,%3};\n"
        : "+f"(d[0]), "+f"(d[1]), "+f"(d[2]), "+f"(d[3])
        : "r"(a[0]), "r"(a[1]), "r"(a[2]), "r"(a[3]), "r"(b0), "r"(b1));
}
__device__ __forceinline__ uint32_t smem_u32(const void* p) {
    uint32_t a;
    asm("{ .reg .u64 t; cvta.to.shared.u64 t, %1; cvt.u32.u64 %0, t; }" : "=r"(a) : "l"(p));
    return a;
}

__global__ void lut_init_kernel() {
    int i = threadIdx.x;
    if (i < 192) {
        int off = i * 192 - (i * (i - 1)) / 2;
        for (int j = i; j < 192; ++j)
            g_lut[off + (j - i)] = (unsigned short)(i | (j << 8));
    }
    if (i < 64) g_lut[TRI + i] = (unsigned short)(i | (192 << 8));
}
__global__ void plut_init_kernel() {
    int p = blockIdx.x * blockDim.x + threadIdx.x;
    if (p < NPAIR)
        g_plut[p] = (unsigned)g_lut[2 * p] | ((unsigned)g_lut[2 * p + 1] << 16);
}

__global__ void embed_kernel(const int* __restrict__ xs, const float* __restrict__ emb,
                             float* __restrict__ c) {
    int t = blockIdx.x * blockDim.x + threadIdx.x;
    int b = t >> 4, v = t & 15;
    if (b >= NB) return;
    const float4* et = (const float4*)emb;
    const int* row = xs + b * NHIST;
    float4 acc = make_float4(0.f, 0.f, 0.f, 0.f);
    for (int h = 0; h < NHIST; ++h) {
        float4 e = et[(size_t)row[h] * 16 + v];
        acc.x += e.x; acc.y += e.y; acc.z += e.z; acc.w += e.w;
    }
    *(float4*)(c + (size_t)b * ALLD + 128 + v * 4) = acc;
}

// ---------------- pipelined small GEMM: tile 64x64x32, tf32, 4-stage cp.async ----------
#define GS_SMEM 71680
template<int ACT, int RNA>
__global__ void __launch_bounds__(256) gemm_s(
    const float* __restrict__ A, const float* __restrict__ Bw,
    const float* __restrict__ bias, float* __restrict__ C,
    int N, int K, int ldc)
{
    extern __shared__ unsigned smU[];
    const int tid = threadIdx.x;
    const int warp = tid >> 5, lane = tid & 31;
    const int g = lane >> 2, tg = lane & 3;
    const int wm = warp & 1, wn = warp >> 1;
    const int m0 = blockIdx.y * 64, n0 = blockIdx.x * 64;
    const uint32_t sbase = smem_u32(smU);
    float acc[2][2][4] = {};

#define LOAD_SM(cc) do { \
        int _s = (cc) & 3; \
        uint32_t _da = sbase + _s * 9216; \
        _Pragma("unroll") \
        for (int _q = 0; _q < 2; ++_q) { \
            int _i = tid + _q * 256, _ar = _i >> 3, _a4 = _i & 7; \
            asm volatile("cp.async.cg.shared.global [%0], [%1], 16;" \
                :: "r"(_da + (_ar * 36 + _a4 * 4) * 4), \
                   "l"(A + (size_t)(m0 + _ar) * K + (cc) * 32 + _a4 * 4) : "memory"); \
        } \
        uint32_t _db = sbase + 36864 + _s * 8704; \
        _Pragma("unroll") \
        for (int _q = 0; _q < 2; ++_q) { \
            int _i = tid + _q * 256, _br = _i >> 4, _b4 = _i & 15; \
            asm volatile("cp.async.cg.shared.global [%0], [%1], 16;" \
                :: "r"(_db + (_br * 68 + _b4 * 4) * 4), \
                   "l"(Bw + (size_t)((cc) * 32 + _br) * N + n0 + _b4 * 4) : "memory"); \
        } \
    } while (0)

    const int nch = K / 32;
    LOAD_SM(0); asm volatile("cp.async.commit_group;" ::: "memory");
    LOAD_SM(1); asm volatile("cp.async.commit_group;" ::: "memory");

    for (int c = 0; c < nch; ++c) {
        if (c + 2 < nch) LOAD_SM(c + 2);
        asm volatile("cp.async.commit_group;" ::: "memory");
        asm volatile("cp.async.wait_group 2;" ::: "memory");
        __syncthreads();
        const unsigned* As = smU + (c & 3) * 2304;
        const unsigned* Bs = smU + 9216 + (c & 3) * 2176;
#pragma unroll
        for (int k8 = 0; k8 < 4; ++k8) {
            const int kk = k8 * 8 + tg;
            unsigned a[2][4];
#pragma unroll
            for (int mt = 0; mt < 2; ++mt) {
                int r = (wm * 32 + mt * 16 + g) * 36;
                a[mt][0] = As[r + kk];
                a[mt][1] = As[r + 288 + kk];
                a[mt][2] = As[r + kk + 4];
                a[mt][3] = As[r + 288 + kk + 4];
                if (RNA) {
#pragma unroll
                    for (int q = 0; q < 4; ++q)
                        a[mt][q] = f2tf32(__uint_as_float(a[mt][q]));
                }
            }
#pragma unroll
            for (int nt = 0; nt < 2; ++nt) {
                int col = wn * 16 + nt * 8 + g;
                unsigned b0 = Bs[kk * 68 + col];
                unsigned b1 = Bs[(kk + 4) * 68 + col];
                if (RNA) {
                    b0 = f2tf32(__uint_as_float(b0));
                    b1 = f2tf32(__uint_as_float(b1));
                }
                mma_tf32(acc[0][nt], a[0], b0, b1);
                mma_tf32(acc[1][nt], a[1], b0, b1);
            }
        }
    }
#pragma unroll
    for (int mt = 0; mt < 2; ++mt) {
        int r0 = m0 + wm * 32 + mt * 16 + g;
#pragma unroll
        for (int nt = 0; nt < 2; ++nt) {
            int col = n0 + wn * 16 + nt * 8 + tg * 2;
            float bi0 = bias[col], bi1 = bias[col + 1];
            float v0 = acc[mt][nt][0] + bi0, v1 = acc[mt][nt][1] + bi1;
            float v2 = acc[mt][nt][2] + bi0, v3 = acc[mt][nt][3] + bi1;
            if (ACT) { v0 = fmaxf(v0, 0.f); v1 = fmaxf(v1, 0.f); v2 = fmaxf(v2, 0.f); v3 = fmaxf(v3, 0.f); }
            *(float2*)(C + (size_t)r0 * ldc + col) = make_float2(v0, v1);
            *(float2*)(C + (size_t)(r0 + 8) * ldc + col) = make_float2(v2, v3);
        }
    }
#undef LOAD_SM
}

// ---------------- small GEMM, tile 32x64x32 (for N=64 layers; doubles grid) ----------
#define GS32_SMEM 53248
template<int ACT, int RNA>
__global__ void __launch_bounds__(256) gemm_s32(
    const float* __restrict__ A, const float* __restrict__ Bw,
    const float* __restrict__ bias, float* __restrict__ C,
    int N, int K, int ldc)
{
    extern __shared__ unsigned smU[];
    const int tid = threadIdx.x;
    const int warp = tid >> 5, lane = tid & 31;
    const int g = lane >> 2, tg = lane & 3;
    const int wm = warp & 1, wn = warp >> 1;
    const int m0 = blockIdx.y * 32, n0 = blockIdx.x * 64;
    const uint32_t sbase = smem_u32(smU);
    float acc[2][4] = {};

#define LOAD_S32(cc) do { \
        int _s = (cc) & 3; \
        uint32_t _da = sbase + _s * 13312; \
        { \
            int _ar = tid >> 3, _a4 = tid & 7; \
            asm volatile("cp.async.cg.shared.global [%0], [%1], 16;" \
                :: "r"(_da + (_ar * 36 + _a4 * 4) * 4), \
                   "l"(A + (size_t)(m0 + _ar) * K + (cc) * 32 + _a4 * 4) : "memory"); \
        } \
        uint32_t _db = _da + 4608; \
        _Pragma("unroll") \
        for (int _q = 0; _q < 2; ++_q) { \
            int _i = tid + _q * 256, _br = _i >> 4, _b4 = _i & 15; \
            asm volatile("cp.async.cg.shared.global [%0], [%1], 16;" \
                :: "r"(_db + (_br * 68 + _b4 * 4) * 4), \
                   "l"(Bw + (size_t)((cc) * 32 + _br) * N + n0 + _b4 * 4) : "memory"); \
        } \
    } while (0)

    const int nch = K / 32;
    LOAD_S32(0); asm volatile("cp.async.commit_group;" ::: "memory");
    LOAD_S32(1); asm volatile("cp.async.commit_group;" ::: "memory");

    for (int c = 0; c < nch; ++c) {
        if (c + 2 < nch) LOAD_S32(c + 2);
        asm volatile("cp.async.commit_group;" ::: "memory");
        asm volatile("cp.async.wait_group 2;" ::: "memory");
        __syncthreads();
        const unsigned* As = smU + (c & 3) * 3328;
        const unsigned* Bs = As + 1152;
#pragma unroll
        for (int k8 = 0; k8 < 4; ++k8) {
            const int kk = k8 * 8 + tg;
            unsigned a[4];
            {
                int r = (wm * 16 + g) * 36;
                a[0] = As[r + kk];
                a[1] = As[r + 288 + kk];
                a[2] = As[r + kk + 4];
                a[3] = As[r + 288 + kk + 4];
                if (RNA) {
#pragma unroll
                    for (int q = 0; q < 4; ++q) a[q] = f2tf32(__uint_as_float(a[q]));
                }
            }
#pragma unroll
            for (int nt = 0; nt < 2; ++nt) {
                int col = wn * 16 + nt * 8 + g;
                unsigned b0 = Bs[kk * 68 + col];
                unsigned b1 = Bs[(kk + 4) * 68 + col];
                if (RNA) {
                    b0 = f2tf32(__uint_as_float(b0));
                    b1 = f2tf32(__uint_as_float(b1));
                }
                mma_tf32(acc[nt], a, b0, b1);
            }
        }
    }
    {
        int r0 = m0 + wm * 16 + g;
#pragma unroll
        for (int nt = 0; nt < 2; ++nt) {
            int col = n0 + wn * 16 + nt * 8 + tg * 2;
            float bi0 = bias[col], bi1 = bias[col + 1];
            float v0 = acc[nt][0] + bi0, v1 = acc[nt][1] + bi1;
            float v2 = acc[nt][2] + bi0, v3 = acc[nt][3] + bi1;
            if (ACT) { v0 = fmaxf(v0, 0.f); v1 = fmaxf(v1, 0.f); v2 = fmaxf(v2, 0.f); v3 = fmaxf(v3, 0.f); }
            *(float2*)(C + (size_t)r0 * ldc + col) = make_float2(v0, v1);
            *(float2*)(C + (size_t)(r0 + 8) * ldc + col) = make_float2(v2, v3);
        }
    }
#undef LOAD_S32
}

__global__ void bn_stats_kernel(const float* __restrict__ z) {
    __shared__ float ssum[256], ssq[256];
    int j = blockIdx.x;
    float s = 0.f, q = 0.f;
    for (int b = threadIdx.x; b < NB; b += 256) {
        float v = z[(size_t)b * 64 + j];
        s += v; q += v * v;
    }
    ssum[threadIdx.x] = s; ssq[threadIdx.x] = q;
    __syncthreads();
    for (int o = 128; o > 0; o >>= 1) {
        if (threadIdx.x < o) {
            ssum[threadIdx.x] += ssum[threadIdx.x + o];
            ssq[threadIdx.x]  += ssq[threadIdx.x + o];
        }
        __syncthreads();
    }
    if (threadIdx.x == 0) {
        float m = ssum[0] * (1.f / NB);
        g_mu[j] = m;
        g_rs[j] = rsqrtf(ssq[0] * (1.f / NB) - m * m + 1e-5f);
    }
}

__global__ void bn_apply_kernel(const float* __restrict__ z,
                                const float* __restrict__ gamma,
                                const float* __restrict__ beta,
                                float* __restrict__ c, float* __restrict__ outx) {
    int idx = blockIdx.x * blockDim.x + threadIdx.x;
    if (idx >= NB * 64) return;
    int b = idx >> 6, j = idx & 63;
    float v = gamma[j] * (z[idx] - g_mu[j]) * g_rs[j] + beta[j];
    c[(size_t)b * ALLD + 64 + j] = v;
    if (outx) outx[idx] = v;
}

// ---------------- materialize interaction matrix, layout [mb][ch][m][k2] ----------------
#define AGEN_SMEM (193 * 129 * 4)
__global__ void __launch_bounds__(256) agen_kernel(const float* __restrict__ cbuf,
                                                   unsigned* __restrict__ At) {
    extern __shared__ float ct[];
    const int mb = blockIdx.x, kg = blockIdx.y;
    const int tid = threadIdx.x;
    for (int idx = tid; idx < 128 * 192; idx += 256) {
        int m = idx / 192, j = idx % 192;
        ct[j * 129 + m] = cbuf[(size_t)((size_t)mb * 128 + m) * ALLD + j];
    }
    for (int m = tid; m < 128; m += 256) ct[192 * 129 + m] = 1.0f;
    __syncthreads();
    const int m = tid & 127, half = tid >> 7;
    int ch0 = kg * 73, ch1 = ch0 + 73; if (ch1 > NCH) ch1 = NCH;
    for (int ch = ch0; ch < ch1; ++ch) {
        uint4* dst4 = (uint4*)(At + (((size_t)mb * NCH + ch) << 11));
        unsigned v[8];
#pragma unroll
        for (int k2l = 0; k2l < 8; ++k2l) {
            unsigned pp = g_plut[ch * 16 + half * 8 + k2l];
            int i0 = pp & 255, j0 = (pp >> 8) & 255;
            int i1 = (pp >> 16) & 255, j1 = pp >> 24;
            v[k2l] = pk(ct[i0 * 129 + m] * ct[j0 * 129 + m],
                        ct[i1 * 129 + m] * ct[j1 * 129 + m]);
        }
        dst4[m * 4 + half * 2 + 0] = make_uint4(v[0], v[1], v[2], v[3]);
        dst4[m * 4 + half * 2 + 1] = make_uint4(v[4], v[5], v[6], v[7]);
    }
}

// ---------------- tw1 -> bf16x2 block layout [nblk][ch][k2][n] ----------------
__global__ void __launch_bounds__(256) bprep_kernel(const float* __restrict__ w,
                                                    unsigned* __restrict__ Bt) {
    const int ch = blockIdx.x, nb = blockIdx.y, n = threadIdx.x;
    unsigned* dst = Bt + (((size_t)nb * NCH + ch) << 12);
    const float* src = w + (size_t)ch * 32 * TOP1N + nb * 256 + n;
#pragma unroll
    for (int k2 = 0; k2 < 16; ++k2) {
        float lo = src[(size_t)(2 * k2) * TOP1N];
        float hi = src[(size_t)(2 * k2 + 1) * TOP1N];
        dst[k2 * 256 + n] = pk(lo, hi);
    }
}

// ---------------- big GEMM: t1 = relu(A @ tw1 + tb1), 128x256 tile, ldmatrix A ----------
#define A_STRU 20                      // uints per m-row (80 B, conflict-free LDSM)
#define A_SLOTU (128 * A_STRU)         // 2560 uints = 10240 B
#define GB_STR 264
#define GB_SLOTU (16 * GB_STR)         // 4224 uints = 16896 B
#define GB_BASEU (4 * A_SLOTU)         // 10240 uints
#define G2_SMEM ((4 * A_SLOTU + 4 * GB_SLOTU) * 4)   // 108544 B

__global__ void __launch_bounds__(256, 1) big_gemm2(
    const unsigned* __restrict__ At, const unsigned* __restrict__ Bt,
    const float* __restrict__ tb1, float* __restrict__ t1)
{
    extern __shared__ unsigned sm2[];
    const int tid = threadIdx.x, warp = tid >> 5, lane = tid & 31;
    const int g = lane >> 2, tg = lane & 3;
    const int wm = warp & 1, wn = warp >> 1;
    const int nb = blockIdx.x, mb = blockIdx.y;
    const uint32_t sbase = smem_u32(sm2);
    const char* Ab = (const char*)(At + (((size_t)mb * NCH) << 11));
    const char* Bb = (const char*)(Bt + (((size_t)nb * NCH) << 12));
    const uint32_t lmoff = ((lane & 15) * A_STRU + (lane >> 4) * 4) * 4;   // bytes

    float acc[4][8][4] = {};

#define LOAD_CHUNK(ch) do { \
        int _slot = (ch) & 3; \
        uint32_t _da = sbase + _slot * (A_SLOTU * 4); \
        const char* _sa = Ab + (size_t)(ch) * 8192; \
        _Pragma("unroll") \
        for (int _q = 0; _q < 2; ++_q) { \
            int _gi = _q * 256 + tid, _m = _gi >> 2, _sg = _gi & 3; \
            asm volatile("cp.async.cg.shared.global [%0], [%1], 16;" \
                :: "r"(_da + _m * 80 + _sg * 16), "l"(_sa + _gi * 16) : "memory"); \
        } \
        uint32_t _db = sbase + GB_BASEU * 4 + _slot * (GB_SLOTU * 4); \
        const char* _sb = Bb + (size_t)(ch) * 16384; \
        _Pragma("unroll") \
        for (int _q = 0; _q < 4; ++_q) { \
            int _gi = _q * 256 + tid, _k2 = _gi >> 6, _i = _gi & 63; \
            asm volatile("cp.async.cg.shared.global [%0], [%1], 16;" \
                :: "r"(_db + _k2 * 1056 + _i * 16), "l"(_sb + _gi * 16) : "memory"); \
        } \
    } while (0)

    LOAD_CHUNK(0); asm volatile("cp.async.commit_group;" ::: "memory");
    LOAD_CHUNK(1); asm volatile("cp.async.commit_group;" ::: "memory");

    for (int ch = 0; ch < NCH; ++ch) {
        if (ch + 2 < NCH) LOAD_CHUNK(ch + 2);
        asm volatile("cp.async.commit_group;" ::: "memory");
        asm volatile("cp.async.wait_group 2;" ::: "memory");
        __syncthreads();
        const uint32_t Ab_s = sbase + (ch & 3) * (A_SLOTU * 4);
        const unsigned* Bs = sm2 + GB_BASEU + (ch & 3) * GB_SLOTU;
#pragma unroll
        for (int ks = 0; ks < 2; ++ks) {
            unsigned af[4][4];
#pragma unroll
            for (int mt = 0; mt < 4; ++mt) {
                uint32_t ad = Ab_s + (wm * 64 + mt * 16) * 80 + ks * 32 + lmoff;
                asm volatile("ldmatrix.sync.aligned.m8n8.x4.shared.b16 {%0,%1,%2,%3}, [%4];"
                    : "=r"(af[mt][0]), "=r"(af[mt][1]), "=r"(af[mt][2]), "=r"(af[mt][3])
                    : "r"(ad));
            }
            const int kb = (ks * 8 + tg) * GB_STR + wn * 64 + g;
#pragma unroll
            for (int nt = 0; nt < 8; ++nt) {
                unsigned b0 = Bs[kb + nt * 8];
                unsigned b1 = Bs[kb + nt * 8 + 4 * GB_STR];
#pragma unroll
                for (int mt = 0; mt < 4; ++mt)
                    mma_bf16(acc[mt][nt], af[mt], b0, b1);
            }
        }
    }

    const int m0 = mb * 128, n0 = nb * 256;
#pragma unroll
    for (int mt = 0; mt < 4; ++mt) {
        int r0 = m0 + wm * 64 + mt * 16 + g;
#pragma unroll
        for (int nt = 0; nt < 8; ++nt) {
            int col = n0 + wn * 64 + nt * 8 + tg * 2;
            float bi0 = tb1[col], bi1 = tb1[col + 1];
            *(float2*)(t1 + (size_t)r0 * TOP1N + col) =
                make_float2(fmaxf(acc[mt][nt][0] + bi0, 0.f), fmaxf(acc[mt][nt][1] + bi1, 0.f));
            *(float2*)(t1 + (size_t)(r0 + 8) * TOP1N + col) =
                make_float2(fmaxf(acc[mt][nt][2] + bi0, 0.f), fmaxf(acc[mt][nt][3] + bi1, 0.f));
        }
    }
#undef LOAD_CHUNK
}

__global__ void top3_kernel(const float* __restrict__ t2, const float* __restrict__ w3,
                            const float* __restrict__ b3, float* __restrict__ out) {
    int gw = (blockIdx.x * blockDim.x + threadIdx.x) >> 5;
    int lane = threadIdx.x & 31;
    if (gw >= NB) return;
    const float* r = t2 + (size_t)gw * TOP2N;
    float s = 0.f;
#pragma unroll
    for (int i = 0; i < TOP2N / 32; ++i)
        s = fmaf(r[lane + 32 * i], w3[lane + 32 * i], s);
#pragma unroll
    for (int o = 16; o > 0; o >>= 1) s += __shfl_xor_sync(0xffffffffu, s, o);
    if (lane == 0) out[gw] = 1.f / (1.f + expf(-(s + b3[0])));
}

extern "C" void kernel_launch(void* const* d_in, const int* in_sizes, int n_in,
                              void* d_out, int out_size) {
    const int*   xs    = (const int*)  d_in[0];
    const float* xd    = (const float*)d_in[1];
    const float* xep   = (const float*)d_in[2];
    const float* emb   = (const float*)d_in[3];
    const float* pw1   = (const float*)d_in[4];
    const float* pb1   = (const float*)d_in[5];
    const float* pw2   = (const float*)d_in[6];
    const float* pb2   = (const float*)d_in[7];
    const float* gamma = (const float*)d_in[8];
    const float* beta  = (const float*)d_in[9];
    const float* bw1   = (const float*)d_in[10];
    const float* bb1   = (const float*)d_in[11];
    const float* bw2   = (const float*)d_in[12];
    const float* bb2   = (const float*)d_in[13];
    const float* tw1   = (const float*)d_in[14];
    const float* tb1   = (const float*)d_in[15];
    const float* tw2   = (const float*)d_in[16];
    const float* tb2   = (const float*)d_in[17];
    const float* tw3   = (const float*)d_in[18];
    const float* tb3   = (const float*)d_in[19];
    float* out = (float*)d_out;

    float *h_p, *z_p, *bh_p, *c_p, *t1_p, *t2_p;
    unsigned *at_p, *btb_p;
    cudaGetSymbolAddress((void**)&h_p,  g_h);
    cudaGetSymbolAddress((void**)&z_p,  g_z);
    cudaGetSymbolAddress((void**)&bh_p, g_bh);
    cudaGetSymbolAddress((void**)&c_p,  g_c);
    cudaGetSymbolAddress((void**)&t1_p, g_t1);
    cudaGetSymbolAddress((void**)&t2_p, g_t2);
    cudaGetSymbolAddress((void**)&at_p, g_at);
    cudaGetSymbolAddress((void**)&btb_p, g_btb);

    float* xemb = (out_size >= NB + NB * 64) ? (out + NB) : nullptr;

    static cudaStream_t s1 = nullptr, s2 = nullptr;
    static cudaEvent_t e0 = nullptr, e1 = nullptr, e2 = nullptr;
    if (!s1) {
        cudaStreamCreateWithFlags(&s1, cudaStreamNonBlocking);
        cudaStreamCreateWithFlags(&s2, cudaStreamNonBlocking);
        cudaEventCreateWithFlags(&e0, cudaEventDisableTiming);
        cudaEventCreateWithFlags(&e1, cudaEventDisableTiming);
        cudaEventCreateWithFlags(&e2, cudaEventDisableTiming);
        cudaFuncSetAttribute(gemm_s<1, 1>, cudaFuncAttributeMaxDynamicSharedMemorySize, GS_SMEM);
        cudaFuncSetAttribute(gemm_s<1, 0>, cudaFuncAttributeMaxDynamicSharedMemorySize, GS_SMEM);
        cudaFuncSetAttribute(gemm_s32<0, 1>, cudaFuncAttributeMaxDynamicSharedMemorySize, GS32_SMEM);
        cudaFuncSetAttribute(gemm_s32<1, 0>, cudaFuncAttributeMaxDynamicSharedMemorySize, GS32_SMEM);
        cudaFuncSetAttribute(agen_kernel, cudaFuncAttributeMaxDynamicSharedMemorySize, AGEN_SMEM);
        cudaFuncSetAttribute(big_gemm2, cudaFuncAttributeMaxDynamicSharedMemorySize, G2_SMEM);
    }

    // fork: proj chain on s1, bottom chain on s2, rest on main
    cudaEventRecord(e0, 0);
    cudaStreamWaitEvent(s1, e0, 0);
    cudaStreamWaitEvent(s2, e0, 0);

    // s1: proj (tf32-rna) -> bn -> x_embed
    gemm_s<1, 1><<<dim3(4, 64), 256, GS_SMEM, s1>>>(xep, pw1, pb1, h_p, 256, 768, 256);
    gemm_s32<0, 1><<<dim3(1, 128), 256, GS32_SMEM, s1>>>(h_p, pw2, pb2, z_p, 64, 256, 64);
    bn_stats_kernel<<<64, 256, 0, s1>>>(z_p);
    bn_apply_kernel<<<(NB * 64) / 256, 256, 0, s1>>>(z_p, gamma, beta, c_p, xemb);

    // s2: bottom (tf32-trunc)
    gemm_s<1, 0><<<dim3(8, 64), 256, GS_SMEM, s2>>>(xd, bw1, bb1, bh_p, 512, 256, 512);
    gemm_s32<1, 0><<<dim3(1, 128), 256, GS32_SMEM, s2>>>(bh_p, bw2, bb2, c_p, 64, 512, ALLD);

    // main: luts, weight prep, embedding
    lut_init_kernel<<<1, 192>>>();
    plut_init_kernel<<<(NPAIR + 255) / 256, 256>>>();
    bprep_kernel<<<dim3(NCH, 4), 256>>>(tw1, btb_p);
    embed_kernel<<<(NB * 16) / 256, 256>>>(xs, emb, c_p);

    // join
    cudaEventRecord(e1, s1);
    cudaEventRecord(e2, s2);
    cudaStreamWaitEvent(0, e1, 0);
    cudaStreamWaitEvent(0, e2, 0);

    // materialize interaction matrix, then pipelined bf16 GEMM (single launches)
    agen_kernel<<<dim3(32, 8), 256, AGEN_SMEM>>>(c_p, at_p);
    big_gemm2<<<dim3(4, 32), 256, G2_SMEM>>>(at_p, btb_p, tb1, t1_p);

    // top2 (tf32-trunc) + top3
    gemm_s<1, 0><<<dim3(8, 64), 256, GS_SMEM>>>(t1_p, tw2, tb2, t2_p, 512, 1024, 512);
    top3_kernel<<<(NB * 32) / 256, 256>>>(t2_p, tw3, tb3, out);
}

// round 16
// speedup vs baseline: 1.1315x; 1.0675x over previous
#include <cstdint>
#include <cuda_runtime.h>
#include <cuda_bf16.h>
#include <math.h>

#define NB 4096
#define NHIST 50
#define ALLD 192
#define TRI 18528
#define OUTD 18592
#define TOP1N 1024
#define TOP2N 512
#define NPAIR (OUTD / 2)
#define NCH 581            // 18592 / 32 exactly

__device__ float g_h [NB * 256];
__device__ float g_z [NB * 64];
__device__ float g_mu[64];
__device__ float g_rs[64];
__device__ float g_bh[NB * 512];
__device__ float g_c [NB * ALLD];
__device__ float g_t1[NB * TOP1N];
__device__ float g_t2[NB * TOP2N];
__device__ unsigned short g_lut[OUTD];
__device__ unsigned g_plut[NPAIR];
// interaction matrix, bf16x2, block layout [mblk=32][ch=581][k2=16][m=128]
__device__ unsigned g_at[(size_t)32 * NCH * 2048];
// tw1 bf16x2, block layout [nblk=4][ch=581][k2=16][n=256]
__device__ unsigned g_btb[(size_t)4 * NCH * 4096];

// ---------------- helpers ----------------
__device__ __forceinline__ unsigned f2tf32(float x) {
    unsigned r; asm("cvt.rna.tf32.f32 %0, %1;" : "=r"(r) : "f"(x)); return r;
}
__device__ __forceinline__ unsigned pk(float lo, float hi) {
    unsigned r; asm("cvt.rn.bf16x2.f32 %0, %1, %2;" : "=r"(r) : "f"(hi), "f"(lo)); return r;
}
__device__ __forceinline__ void mma_tf32(float* d, const unsigned* a, unsigned b0, unsigned b1) {
    asm volatile("mma.sync.aligned.m16n8k8.row.col.f32.tf32.tf32.f32 "
        "{%0,%1,%2,%3}, {%4,%5,%6,%7}, {%8,%9}, {%0,%1,%2,%3};\n"
        : "+f"(d[0]), "+f"(d[1]), "+f"(d[2]), "+f"(d[3])
        : "r"(a[0]), "r"(a[1]), "r"(a[2]), "r"(a[3]), "r"(b0), "r"(b1));
}
__device__ __forceinline__ void mma_bf16(float* d, const unsigned* a, unsigned b0, unsigned b1) {
    asm volatile("mma.sync.aligned.m16n8k16.row.col.f32.bf16.bf16.f32 "
        "{%0,%1,%2,%3}, {%4,%5,%6,%7}, {%8,%9}, {%0,%1,%2,%3};\n"
        : "+f"(d[0]), "+f"(d[1]), "+f"(d[2]), "+f"(d[3])
        : "r"(a[0]), "r"(a[1]), "r"(a[2]), "r"(a[3]), "r"(b0), "r"(b1));
}
__device__ __forceinline__ uint32_t smem_u32(const void* p) {
    uint32_t a;
    asm("{ .reg .u64 t; cvta.to.shared.u64 t, %1; cvt.u32.u64 %0, t; }" : "=r"(a) : "l"(p));
    return a;
}

__global__ void lut_init_kernel() {
    int i = threadIdx.x;
    if (i < 192) {
        int off = i * 192 - (i * (i - 1)) / 2;
        for (int j = i; j < 192; ++j)
            g_lut[off + (j - i)] = (unsigned short)(i | (j << 8));
    }
    if (i < 64) g_lut[TRI + i] = (unsigned short)(i | (192 << 8));
}
__global__ void plut_init_kernel() {
    int p = blockIdx.x * blockDim.x + threadIdx.x;
    if (p < NPAIR)
        g_plut[p] = (unsigned)g_lut[2 * p] | ((unsigned)g_lut[2 * p + 1] << 16);
}

__global__ void embed_kernel(const int* __restrict__ xs, const float* __restrict__ emb,
                             float* __restrict__ c) {
    int t = blockIdx.x * blockDim.x + threadIdx.x;
    int b = t >> 4, v = t & 15;
    if (b >= NB) return;
    const float4* et = (const float4*)emb;
    const int* row = xs + b * NHIST;
    float4 acc = make_float4(0.f, 0.f, 0.f, 0.f);
    for (int h = 0; h < NHIST; ++h) {
        float4 e = et[(size_t)row[h] * 16 + v];
        acc.x += e.x; acc.y += e.y; acc.z += e.z; acc.w += e.w;
    }
    *(float4*)(c + (size_t)b * ALLD + 128 + v * 4) = acc;
}

// ---------------- pipelined small GEMM: tile 64x64x32, tf32, 4-stage cp.async ----------
#define GS_SMEM 71680
template<int ACT, int RNA>
__global__ void __launch_bounds__(256) gemm_s(
    const float* __restrict__ A, const float* __restrict__ Bw,
    const float* __restrict__ bias, float* __restrict__ C,
    int N, int K, int ldc)
{
    extern __shared__ unsigned smU[];
    const int tid = threadIdx.x;
    const int warp = tid >> 5, lane = tid & 31;
    const int g = lane >> 2, tg = lane & 3;
    const int wm = warp & 1, wn = warp >> 1;
    const int m0 = blockIdx.y * 64, n0 = blockIdx.x * 64;
    const uint32_t sbase = smem_u32(smU);
    float acc[2][2][4] = {};

#define LOAD_SM(cc) do { \
        int _s = (cc) & 3; \
        uint32_t _da = sbase + _s * 9216; \
        _Pragma("unroll") \
        for (int _q = 0; _q < 2; ++_q) { \
            int _i = tid + _q * 256, _ar = _i >> 3, _a4 = _i & 7; \
            asm volatile("cp.async.cg.shared.global [%0], [%1], 16;" \
                :: "r"(_da + (_ar * 36 + _a4 * 4) * 4), \
                   "l"(A + (size_t)(m0 + _ar) * K + (cc) * 32 + _a4 * 4) : "memory"); \
        } \
        uint32_t _db = sbase + 36864 + _s * 8704; \
        _Pragma("unroll") \
        for (int _q = 0; _q < 2; ++_q) { \
            int _i = tid + _q * 256, _br = _i >> 4, _b4 = _i & 15; \
            asm volatile("cp.async.cg.shared.global [%0], [%1], 16;" \
                :: "r"(_db + (_br * 68 + _b4 * 4) * 4), \
                   "l"(Bw + (size_t)((cc) * 32 + _br) * N + n0 + _b4 * 4) : "memory"); \
        } \
    } while (0)

    const int nch = K / 32;
    LOAD_SM(0); asm volatile("cp.async.commit_group;" ::: "memory");
    LOAD_SM(1); asm volatile("cp.async.commit_group;" ::: "memory");

    for (int c = 0; c < nch; ++c) {
        if (c + 2 < nch) LOAD_SM(c + 2);
        asm volatile("cp.async.commit_group;" ::: "memory");
        asm volatile("cp.async.wait_group 2;" ::: "memory");
        __syncthreads();
        const unsigned* As = smU + (c & 3) * 2304;
        const unsigned* Bs = smU + 9216 + (c & 3) * 2176;
#pragma unroll
        for (int k8 = 0; k8 < 4; ++k8) {
            const int kk = k8 * 8 + tg;
            unsigned a[2][4];
#pragma unroll
            for (int mt = 0; mt < 2; ++mt) {
                int r = (wm * 32 + mt * 16 + g) * 36;
                a[mt][0] = As[r + kk];
                a[mt][1] = As[r + 288 + kk];
                a[mt][2] = As[r + kk + 4];
                a[mt][3] = As[r + 288 + kk + 4];
                if (RNA) {
#pragma unroll
                    for (int q = 0; q < 4; ++q)
                        a[mt][q] = f2tf32(__uint_as_float(a[mt][q]));
                }
            }
#pragma unroll
            for (int nt = 0; nt < 2; ++nt) {
                int col = wn * 16 + nt * 8 + g;
                unsigned b0 = Bs[kk * 68 + col];
                unsigned b1 = Bs[(kk + 4) * 68 + col];
                if (RNA) {
                    b0 = f2tf32(__uint_as_float(b0));
                    b1 = f2tf32(__uint_as_float(b1));
                }
                mma_tf32(acc[0][nt], a[0], b0, b1);
                mma_tf32(acc[1][nt], a[1], b0, b1);
            }
        }
    }
#pragma unroll
    for (int mt = 0; mt < 2; ++mt) {
        int r0 = m0 + wm * 32 + mt * 16 + g;
#pragma unroll
        for (int nt = 0; nt < 2; ++nt) {
            int col = n0 + wn * 16 + nt * 8 + tg * 2;
            float bi0 = bias[col], bi1 = bias[col + 1];
            float v0 = acc[mt][nt][0] + bi0, v1 = acc[mt][nt][1] + bi1;
            float v2 = acc[mt][nt][2] + bi0, v3 = acc[mt][nt][3] + bi1;
            if (ACT) { v0 = fmaxf(v0, 0.f); v1 = fmaxf(v1, 0.f); v2 = fmaxf(v2, 0.f); v3 = fmaxf(v3, 0.f); }
            *(float2*)(C + (size_t)r0 * ldc + col) = make_float2(v0, v1);
            *(float2*)(C + (size_t)(r0 + 8) * ldc + col) = make_float2(v2, v3);
        }
    }
#undef LOAD_SM
}

// ---------------- small GEMM, tile 32x64x32 (for N=64 layers; doubles grid) ----------
#define GS32_SMEM 53248
template<int ACT, int RNA>
__global__ void __launch_bounds__(256) gemm_s32(
    const float* __restrict__ A, const float* __restrict__ Bw,
    const float* __restrict__ bias, float* __restrict__ C,
    int N, int K, int ldc)
{
    extern __shared__ unsigned smU[];
    const int tid = threadIdx.x;
    const int warp = tid >> 5, lane = tid & 31;
    const int g = lane >> 2, tg = lane & 3;
    const int wm = warp & 1, wn = warp >> 1;
    const int m0 = blockIdx.y * 32, n0 = blockIdx.x * 64;
    const uint32_t sbase = smem_u32(smU);
    float acc[2][4] = {};

#define LOAD_S32(cc) do { \
        int _s = (cc) & 3; \
        uint32_t _da = sbase + _s * 13312; \
        { \
            int _ar = tid >> 3, _a4 = tid & 7; \
            asm volatile("cp.async.cg.shared.global [%0], [%1], 16;" \
                :: "r"(_da + (_ar * 36 + _a4 * 4) * 4), \
                   "l"(A + (size_t)(m0 + _ar) * K + (cc) * 32 + _a4 * 4) : "memory"); \
        } \
        uint32_t _db = _da + 4608; \
        _Pragma("unroll") \
        for (int _q = 0; _q < 2; ++_q) { \
            int _i = tid + _q * 256, _br = _i >> 4, _b4 = _i & 15; \
            asm volatile("cp.async.cg.shared.global [%0], [%1], 16;" \
                :: "r"(_db + (_br * 68 + _b4 * 4) * 4), \
                   "l"(Bw + (size_t)((cc) * 32 + _br) * N + n0 + _b4 * 4) : "memory"); \
        } \
    } while (0)

    const int nch = K / 32;
    LOAD_S32(0); asm volatile("cp.async.commit_group;" ::: "memory");
    LOAD_S32(1); asm volatile("cp.async.commit_group;" ::: "memory");

    for (int c = 0; c < nch; ++c) {
        if (c + 2 < nch) LOAD_S32(c + 2);
        asm volatile("cp.async.commit_group;" ::: "memory");
        asm volatile("cp.async.wait_group 2;" ::: "memory");
        __syncthreads();
        const unsigned* As = smU + (c & 3) * 3328;
        const unsigned* Bs = As + 1152;
#pragma unroll
        for (int k8 = 0; k8 < 4; ++k8) {
            const int kk = k8 * 8 + tg;
            unsigned a[4];
            {
                int r = (wm * 16 + g) * 36;
                a[0] = As[r + kk];
                a[1] = As[r + 288 + kk];
                a[2] = As[r + kk + 4];
                a[3] = As[r + 288 + kk + 4];
                if (RNA) {
#pragma unroll
                    for (int q = 0; q < 4; ++q) a[q] = f2tf32(__uint_as_float(a[q]));
                }
            }
#pragma unroll
            for (int nt = 0; nt < 2; ++nt) {
                int col = wn * 16 + nt * 8 + g;
                unsigned b0 = Bs[kk * 68 + col];
                unsigned b1 = Bs[(kk + 4) * 68 + col];
                if (RNA) {
                    b0 = f2tf32(__uint_as_float(b0));
                    b1 = f2tf32(__uint_as_float(b1));
                }
                mma_tf32(acc[nt], a, b0, b1);
            }
        }
    }
    {
        int r0 = m0 + wm * 16 + g;
#pragma unroll
        for (int nt = 0; nt < 2; ++nt) {
            int col = n0 + wn * 16 + nt * 8 + tg * 2;
            float bi0 = bias[col], bi1 = bias[col + 1];
            float v0 = acc[nt][0] + bi0, v1 = acc[nt][1] + bi1;
            float v2 = acc[nt][2] + bi0, v3 = acc[nt][3] + bi1;
            if (ACT) { v0 = fmaxf(v0, 0.f); v1 = fmaxf(v1, 0.f); v2 = fmaxf(v2, 0.f); v3 = fmaxf(v3, 0.f); }
            *(float2*)(C + (size_t)r0 * ldc + col) = make_float2(v0, v1);
            *(float2*)(C + (size_t)(r0 + 8) * ldc + col) = make_float2(v2, v3);
        }
    }
#undef LOAD_S32
}

__global__ void bn_stats_kernel(const float* __restrict__ z) {
    __shared__ float ssum[256], ssq[256];
    int j = blockIdx.x;
    float s = 0.f, q = 0.f;
    for (int b = threadIdx.x; b < NB; b += 256) {
        float v = z[(size_t)b * 64 + j];
        s += v; q += v * v;
    }
    ssum[threadIdx.x] = s; ssq[threadIdx.x] = q;
    __syncthreads();
    for (int o = 128; o > 0; o >>= 1) {
        if (threadIdx.x < o) {
            ssum[threadIdx.x] += ssum[threadIdx.x + o];
            ssq[threadIdx.x]  += ssq[threadIdx.x + o];
        }
        __syncthreads();
    }
    if (threadIdx.x == 0) {
        float m = ssum[0] * (1.f / NB);
        g_mu[j] = m;
        g_rs[j] = rsqrtf(ssq[0] * (1.f / NB) - m * m + 1e-5f);
    }
}

__global__ void bn_apply_kernel(const float* __restrict__ z,
                                const float* __restrict__ gamma,
                                const float* __restrict__ beta,
                                float* __restrict__ c, float* __restrict__ outx) {
    int idx = blockIdx.x * blockDim.x + threadIdx.x;
    if (idx >= NB * 64) return;
    int b = idx >> 6, j = idx & 63;
    float v = gamma[j] * (z[idx] - g_mu[j]) * g_rs[j] + beta[j];
    c[(size_t)b * ALLD + 64 + j] = v;
    if (outx) outx[idx] = v;
}

// ---------------- materialize interaction matrix (bf16x2, [mb][ch][k2][m]) ----------------
#define AGEN_SMEM (193 * 129 * 4)
__global__ void __launch_bounds__(256) agen_kernel(const float* __restrict__ cbuf,
                                                   unsigned* __restrict__ At) {
    extern __shared__ float ct[];
    const int mb = blockIdx.x, kg = blockIdx.y;
    const int tid = threadIdx.x;
    for (int idx = tid; idx < 128 * 192; idx += 256) {
        int m = idx / 192, j = idx % 192;
        ct[j * 129 + m] = cbuf[(size_t)(mb * 128 + m) * ALLD + j];
    }
    for (int m = tid; m < 128; m += 256) ct[192 * 129 + m] = 1.0f;
    __syncthreads();
    const int m = tid & 127, half = tid >> 7;
    int ch0 = kg * 73, ch1 = ch0 + 73; if (ch1 > NCH) ch1 = NCH;
    for (int ch = ch0; ch < ch1; ++ch) {
        unsigned* dst = At + (((size_t)mb * NCH + ch) << 11);
#pragma unroll
        for (int k2l = 0; k2l < 8; ++k2l) {
            int k2 = half * 8 + k2l;
            unsigned pp = g_plut[ch * 16 + k2];
            int i0 = pp & 255, j0 = (pp >> 8) & 255;
            int i1 = (pp >> 16) & 255, j1 = pp >> 24;
            unsigned v = pk(ct[i0 * 129 + m] * ct[j0 * 129 + m],
                            ct[i1 * 129 + m] * ct[j1 * 129 + m]);
            dst[k2 * 128 + m] = v;
        }
    }
}

// ---------------- tw1 -> bf16x2 block layout [nblk][ch][k2][n] ----------------
__global__ void __launch_bounds__(256) bprep_kernel(const float* __restrict__ w,
                                                    unsigned* __restrict__ Bt) {
    const int ch = blockIdx.x, nb = blockIdx.y, n = threadIdx.x;
    unsigned* dst = Bt + (((size_t)nb * NCH + ch) << 12);
    const float* src = w + (size_t)ch * 32 * TOP1N + nb * 256 + n;
#pragma unroll
    for (int k2 = 0; k2 < 16; ++k2) {
        float lo = src[(size_t)(2 * k2) * TOP1N];
        float hi = src[(size_t)(2 * k2 + 1) * TOP1N];
        dst[k2 * 256 + n] = pk(lo, hi);
    }
}

// ---------------- big GEMM: 128x256 tile, 8 chunk-slots, pair-wise sync ----------
#define GA_STR 136
#define GB_STR 264
#define GA_SLOT (16 * GA_STR)          // 2176 uints
#define GB_SLOT (16 * GB_STR)          // 4224 uints
#define NSLOT 8
#define GB_BASE (NSLOT * GA_SLOT)      // 17408 uints
#define G2_SMEM ((NSLOT * (GA_SLOT + GB_SLOT)) * 4)   // 204800 B

__global__ void __launch_bounds__(256, 1) big_gemm2(
    const unsigned* __restrict__ At, const unsigned* __restrict__ Bt,
    const float* __restrict__ tb1, float* __restrict__ t1)
{
    extern __shared__ unsigned sm2[];
    const int tid = threadIdx.x, warp = tid >> 5, lane = tid & 31;
    const int g = lane >> 2, tg = lane & 3;
    const int wm = warp & 1, wn = warp >> 1;
    const int nb = blockIdx.x, mb = blockIdx.y;
    const uint32_t sbase = smem_u32(sm2);
    const char* Ab = (const char*)(At + (((size_t)mb * NCH) << 11));
    const char* Bb = (const char*)(Bt + (((size_t)nb * NCH) << 12));

    float acc[4][8][4] = {};

#define LOAD_CHUNK(ch) do { \
        int _slot = (ch) & (NSLOT - 1); \
        uint32_t _da = sbase + _slot * (GA_SLOT * 4); \
        const char* _sa = Ab + (size_t)(ch) * 8192; \
        _Pragma("unroll") \
        for (int _q = 0; _q < 2; ++_q) { \
            int _gi = _q * 256 + tid, _k2 = _gi >> 5, _i = _gi & 31; \
            asm volatile("cp.async.cg.shared.global [%0], [%1], 16;" \
                :: "r"(_da + _k2 * 544 + _i * 16), "l"(_sa + _gi * 16) : "memory"); \
        } \
        uint32_t _db = sbase + GB_BASE * 4 + _slot * (GB_SLOT * 4); \
        const char* _sb = Bb + (size_t)(ch) * 16384; \
        _Pragma("unroll") \
        for (int _q = 0; _q < 4; ++_q) { \
            int _gi = _q * 256 + tid, _k2 = _gi >> 6, _i = _gi & 63; \
            asm volatile("cp.async.cg.shared.global [%0], [%1], 16;" \
                :: "r"(_db + _k2 * 1056 + _i * 16), "l"(_sb + _gi * 16) : "memory"); \
        } \
    } while (0)

#define COMPUTE_CHUNK(ch) do { \
        const unsigned* As = sm2 + ((ch) & (NSLOT - 1)) * GA_SLOT; \
        const unsigned* Bs = sm2 + GB_BASE + ((ch) & (NSLOT - 1)) * GB_SLOT; \
        _Pragma("unroll") \
        for (int ks = 0; ks < 2; ++ks) { \
            unsigned af[4][4]; \
            const int ka = (ks * 8 + tg) * GA_STR + wm * 64 + g; \
            _Pragma("unroll") \
            for (int mt = 0; mt < 4; ++mt) { \
                int base = ka + mt * 16; \
                af[mt][0] = As[base]; \
                af[mt][1] = As[base + 8]; \
                af[mt][2] = As[base + 4 * GA_STR]; \
                af[mt][3] = As[base + 4 * GA_STR + 8]; \
            } \
            const int kb = (ks * 8 + tg) * GB_STR + wn * 64 + g; \
            _Pragma("unroll") \
            for (int nt = 0; nt < 8; ++nt) { \
                unsigned b0 = Bs[kb + nt * 8]; \
                unsigned b1 = Bs[kb + nt * 8 + 4 * GB_STR]; \
                _Pragma("unroll") \
                for (int mt = 0; mt < 4; ++mt) \
                    mma_bf16(acc[mt][nt], af[mt], b0, b1); \
            } \
        } \
    } while (0)

    LOAD_CHUNK(0); LOAD_CHUNK(1);
    asm volatile("cp.async.commit_group;" ::: "memory");
    LOAD_CHUNK(2); LOAD_CHUNK(3);
    asm volatile("cp.async.commit_group;" ::: "memory");

    for (int c = 0; c < NCH; c += 2) {
        if (c + 4 < NCH) {
            LOAD_CHUNK(c + 4);
            if (c + 5 < NCH) LOAD_CHUNK(c + 5);
        }
        asm volatile("cp.async.commit_group;" ::: "memory");
        asm volatile("cp.async.wait_group 2;" ::: "memory");
        __syncthreads();
        COMPUTE_CHUNK(c);
        if (c + 1 < NCH) COMPUTE_CHUNK(c + 1);
    }

    const int m0 = mb * 128, n0 = nb * 256;
#pragma unroll
    for (int mt = 0; mt < 4; ++mt) {
        int r0 = m0 + wm * 64 + mt * 16 + g;
#pragma unroll
        for (int nt = 0; nt < 8; ++nt) {
            int col = n0 + wn * 64 + nt * 8 + tg * 2;
            float bi0 = tb1[col], bi1 = tb1[col + 1];
            *(float2*)(t1 + (size_t)r0 * TOP1N + col) =
                make_float2(fmaxf(acc[mt][nt][0] + bi0, 0.f), fmaxf(acc[mt][nt][1] + bi1, 0.f));
            *(float2*)(t1 + (size_t)(r0 + 8) * TOP1N + col) =
                make_float2(fmaxf(acc[mt][nt][2] + bi0, 0.f), fmaxf(acc[mt][nt][3] + bi1, 0.f));
        }
    }
#undef LOAD_CHUNK
#undef COMPUTE_CHUNK
}

__global__ void top3_kernel(const float* __restrict__ t2, const float* __restrict__ w3,
                            const float* __restrict__ b3, float* __restrict__ out) {
    int gw = (blockIdx.x * blockDim.x + threadIdx.x) >> 5;
    int lane = threadIdx.x & 31;
    if (gw >= NB) return;
    const float* r = t2 + (size_t)gw * TOP2N;
    float s = 0.f;
#pragma unroll
    for (int i = 0; i < TOP2N / 32; ++i)
        s = fmaf(r[lane + 32 * i], w3[lane + 32 * i], s);
#pragma unroll
    for (int o = 16; o > 0; o >>= 1) s += __shfl_xor_sync(0xffffffffu, s, o);
    if (lane == 0) out[gw] = 1.f / (1.f + expf(-(s + b3[0])));
}

extern "C" void kernel_launch(void* const* d_in, const int* in_sizes, int n_in,
                              void* d_out, int out_size) {
    const int*   xs    = (const int*)  d_in[0];
    const float* xd    = (const float*)d_in[1];
    const float* xep   = (const float*)d_in[2];
    const float* emb   = (const float*)d_in[3];
    const float* pw1   = (const float*)d_in[4];
    const float* pb1   = (const float*)d_in[5];
    const float* pw2   = (const float*)d_in[6];
    const float* pb2   = (const float*)d_in[7];
    const float* gamma = (const float*)d_in[8];
    const float* beta  = (const float*)d_in[9];
    const float* bw1   = (const float*)d_in[10];
    const float* bb1   = (const float*)d_in[11];
    const float* bw2   = (const float*)d_in[12];
    const float* bb2   = (const float*)d_in[13];
    const float* tw1   = (const float*)d_in[14];
    const float* tb1   = (const float*)d_in[15];
    const float* tw2   = (const float*)d_in[16];
    const float* tb2   = (const float*)d_in[17];
    const float* tw3   = (const float*)d_in[18];
    const float* tb3   = (const float*)d_in[19];
    float* out = (float*)d_out;

    float *h_p, *z_p, *bh_p, *c_p, *t1_p, *t2_p;
    unsigned *at_p, *btb_p;
    cudaGetSymbolAddress((void**)&h_p,  g_h);
    cudaGetSymbolAddress((void**)&z_p,  g_z);
    cudaGetSymbolAddress((void**)&bh_p, g_bh);
    cudaGetSymbolAddress((void**)&c_p,  g_c);
    cudaGetSymbolAddress((void**)&t1_p, g_t1);
    cudaGetSymbolAddress((void**)&t2_p, g_t2);
    cudaGetSymbolAddress((void**)&at_p, g_at);
    cudaGetSymbolAddress((void**)&btb_p, g_btb);

    float* xemb = (out_size >= NB + NB * 64) ? (out + NB) : nullptr;

    static cudaStream_t s1 = nullptr, s2 = nullptr;
    static cudaEvent_t e0 = nullptr, e1 = nullptr, e2 = nullptr;
    if (!s1) {
        cudaStreamCreateWithFlags(&s1, cudaStreamNonBlocking);
        cudaStreamCreateWithFlags(&s2, cudaStreamNonBlocking);
        cudaEventCreateWithFlags(&e0, cudaEventDisableTiming);
        cudaEventCreateWithFlags(&e1, cudaEventDisableTiming);
        cudaEventCreateWithFlags(&e2, cudaEventDisableTiming);
        cudaFuncSetAttribute(gemm_s<1, 1>, cudaFuncAttributeMaxDynamicSharedMemorySize, GS_SMEM);
        cudaFuncSetAttribute(gemm_s<1, 0>, cudaFuncAttributeMaxDynamicSharedMemorySize, GS_SMEM);
        cudaFuncSetAttribute(gemm_s32<0, 1>, cudaFuncAttributeMaxDynamicSharedMemorySize, GS32_SMEM);
        cudaFuncSetAttribute(gemm_s32<1, 0>, cudaFuncAttributeMaxDynamicSharedMemorySize, GS32_SMEM);
        cudaFuncSetAttribute(agen_kernel, cudaFuncAttributeMaxDynamicSharedMemorySize, AGEN_SMEM);
        cudaFuncSetAttribute(big_gemm2, cudaFuncAttributeMaxDynamicSharedMemorySize, G2_SMEM);
    }

    // fork: proj chain on s1, bottom chain on s2, rest on main
    cudaEventRecord(e0, 0);
    cudaStreamWaitEvent(s1, e0, 0);
    cudaStreamWaitEvent(s2, e0, 0);

    // s1: proj (tf32-rna) -> bn -> x_embed
    gemm_s<1, 1><<<dim3(4, 64), 256, GS_SMEM, s1>>>(xep, pw1, pb1, h_p, 256, 768, 256);
    gemm_s32<0, 1><<<dim3(1, 128), 256, GS32_SMEM, s1>>>(h_p, pw2, pb2, z_p, 64, 256, 64);
    bn_stats_kernel<<<64, 256, 0, s1>>>(z_p);
    bn_apply_kernel<<<(NB * 64) / 256, 256, 0, s1>>>(z_p, gamma, beta, c_p, xemb);

    // s2: bottom (tf32-trunc)
    gemm_s<1, 0><<<dim3(8, 64), 256, GS_SMEM, s2>>>(xd, bw1, bb1, bh_p, 512, 256, 512);
    gemm_s32<1, 0><<<dim3(1, 128), 256, GS32_SMEM, s2>>>(bh_p, bw2, bb2, c_p, 64, 512, ALLD);

    // main: luts, weight prep, embedding
    lut_init_kernel<<<1, 192>>>();
    plut_init_kernel<<<(NPAIR + 255) / 256, 256>>>();
    bprep_kernel<<<dim3(NCH, 4), 256>>>(tw1, btb_p);
    embed_kernel<<<(NB * 16) / 256, 256>>>(xs, emb, c_p);

    // join
    cudaEventRecord(e1, s1);
    cudaEventRecord(e2, s2);
    cudaStreamWaitEvent(0, e1, 0);
    cudaStreamWaitEvent(0, e2, 0);

    // materialize interaction matrix, then pipelined bf16 GEMM
    agen_kernel<<<dim3(32, 8), 256, AGEN_SMEM>>>(c_p, at_p);
    big_gemm2<<<dim3(4, 32), 256, G2_SMEM>>>(at_p, btb_p, tb1, t1_p);

    // top2 (tf32-trunc) + top3
    gemm_s<1, 0><<<dim3(8, 64), 256, GS_SMEM>>>(t1_p, tw2, tb2, t2_p, 512, 1024, 512);
    top3_kernel<<<(NB * 32) / 256, 256>>>(t2_p, tw3, tb3, out);
}